// round 4
// baseline (speedup 1.0000x reference)
#include <cuda_runtime.h>

#define PHN 7
#define NSAMP 14          // PH * sampling_ratio
#define TPB 256
#define NWARP (TPB/32)
#define CPW 2             // channels per warp iteration

__global__ __launch_bounds__(TPB, 5) void roialign_kernel(
    const float* __restrict__ x, const float* __restrict__ rois,
    float* __restrict__ out, int C, int H, int W)
{
    __shared__ int   s_yl[NSAMP], s_yh[NSAMP];     // pre-multiplied by W
    __shared__ float s_wy0[NSAMP], s_wy1[NSAMP];
    __shared__ int   s_xl[NSAMP], s_xh[NSAMP];
    __shared__ float s_wx0[NSAMP], s_wx1[NSAMP];
    __shared__ int   s_bidx;

    const int k    = blockIdx.x;
    const int tid  = threadIdx.x;
    const int lane = tid & 31;
    const int warp = tid >> 5;

    if (tid == 0) s_bidx = (int)rois[k*5];
    // Per-axis sample tables, matching reference _axis() exactly.
    if (tid < 2*NSAMP) {
        int axis = tid / NSAMP;            // 0 = y, 1 = x
        int n    = tid % NSAMP;
        float limit = axis ? (float)W : (float)H;
        float start = rois[k*5 + (axis ? 1 : 2)] * 0.25f - 0.5f;
        float end   = rois[k*5 + (axis ? 3 : 4)] * 0.25f - 0.5f;
        float bin   = (end - start) * (1.0f/7.0f);
        int p = n >> 1, s = n & 1;
        float coord = start + ((float)p + ((float)s + 0.5f) * 0.5f) * bin;
        float valid = (coord >= -1.0f && coord <= limit) ? 1.0f : 0.0f;
        float c = fmaxf(coord, 0.0f);
        int low0 = (int)floorf(c);
        int lim  = (int)limit;
        bool cap = (low0 >= lim - 1);
        int low  = cap ? lim - 1 : low0;
        int high = cap ? lim - 1 : low0 + 1;
        if (cap) c = (float)low;
        float l = c - (float)low;
        float h = 1.0f - l;
        if (axis) { s_xl[n] = low;     s_xh[n] = high;     s_wx0[n] = h*valid; s_wx1[n] = l*valid; }
        else      { s_yl[n] = low * W; s_yh[n] = high * W; s_wy0[n] = h*valid; s_wy1[n] = l*valid; }
    }
    __syncthreads();

    // Lane-resident x tap: lane l<28 -> sample l>>1, corner l&1.
    const int ll   = (lane < 28) ? lane : 27;
    const int nx   = ll >> 1;
    const int xoff = (ll & 1) ? s_xh[nx] : s_xl[nx];
    const float wx = (lane < 28)
                   ? (((lane & 1) ? s_wx1[nx] : s_wx0[nx]) * 0.25f)
                   : 0.0f;

    // After the 4-lane bin reduction, lanes 0,4,..,24 hold pw=0..6; their
    // output addresses are contiguous floats -> single-wavefront STG.
    const bool wlane = (lane < 28) && ((lane & 3) == 0);
    const int  pw    = lane >> 2;

    // All indices fit in 32 bits (input 20.5M floats, output 12.5M floats).
    const int plane = H * W;
    int idx = (s_bidx * C + warp * CPW) * plane + xoff;   // input index, ch c0
    int oix = (k * C + warp * CPW) * 49 + pw;             // output index, ch c0
    const int istep = NWARP * CPW * plane;
    const int ostep = NWARP * CPW * 49;

    for (int c0 = warp * CPW; c0 < C; c0 += NWARP * CPW, idx += istep, oix += ostep) {
        #pragma unroll
        for (int ph = 0; ph < PHN; ph++) {
            float a0 = 0.0f, a1 = 0.0f;
            #pragma unroll
            for (int j = 0; j < 4; j++) {
                int ny     = 2*ph + (j >> 1);
                int   yoff = (j & 1) ? s_yh[ny]  : s_yl[ny];
                float wy   = (j & 1) ? s_wy1[ny] : s_wy0[ny];
                float v0 = __ldg(x + idx + yoff);
                float v1 = __ldg(x + idx + plane + yoff);
                a0 = fmaf(wy, v0, a0);
                a1 = fmaf(wy, v1, a1);
            }
            a0 *= wx;  a1 *= wx;
            a0 += __shfl_xor_sync(0xffffffffu, a0, 1);
            a1 += __shfl_xor_sync(0xffffffffu, a1, 1);
            a0 += __shfl_xor_sync(0xffffffffu, a0, 2);
            a1 += __shfl_xor_sync(0xffffffffu, a1, 2);
            if (wlane) {
                out[oix + ph * 7]      = a0;
                out[oix + 49 + ph * 7] = a1;
            }
        }
    }
}

extern "C" void kernel_launch(void* const* d_in, const int* in_sizes, int n_in,
                              void* d_out, int out_size)
{
    const float* x    = (const float*)d_in[0];
    const float* rois = (const float*)d_in[1];
    float* out        = (float*)d_out;
    const int K = in_sizes[1] / 5;
    roialign_kernel<<<K, TPB>>>(x, rois, out, 256, 200, 200);
}

// round 6
// speedup vs baseline: 1.3802x; 1.3802x over previous
#include <cuda_runtime.h>

#define PHN 7
#define NSAMP 14          // PH * sampling_ratio
#define TPB 256
#define NWARP (TPB/32)
#define CPW 4             // channels per warp iteration
#define CSPLIT 2          // blocks per roi (channel split)

__global__ __launch_bounds__(TPB, 3) void roialign_kernel(
    const float* __restrict__ x, const float* __restrict__ rois,
    float* __restrict__ out, int C, int H, int W)
{
    __shared__ int   s_yl[NSAMP], s_yh[NSAMP];     // pre-multiplied by W
    __shared__ float s_wy0[NSAMP], s_wy1[NSAMP];
    __shared__ int   s_xl[NSAMP], s_xh[NSAMP];
    __shared__ float s_wx0[NSAMP], s_wx1[NSAMP];
    __shared__ int   s_bidx;

    const int k     = blockIdx.x / CSPLIT;
    const int cbase = (blockIdx.x % CSPLIT) * (C / CSPLIT);
    const int tid  = threadIdx.x;
    const int lane = tid & 31;
    const int warp = tid >> 5;

    if (tid == 0) s_bidx = (int)rois[k*5];
    // Per-axis sample tables, matching reference _axis() exactly.
    if (tid < 2*NSAMP) {
        int axis = tid / NSAMP;            // 0 = y, 1 = x
        int n    = tid % NSAMP;
        float limit = axis ? (float)W : (float)H;
        float start = rois[k*5 + (axis ? 1 : 2)] * 0.25f - 0.5f;
        float end   = rois[k*5 + (axis ? 3 : 4)] * 0.25f - 0.5f;
        float bin   = (end - start) * (1.0f/7.0f);
        int p = n >> 1, s = n & 1;
        float coord = start + ((float)p + ((float)s + 0.5f) * 0.5f) * bin;
        float valid = (coord >= -1.0f && coord <= limit) ? 1.0f : 0.0f;
        float c = fmaxf(coord, 0.0f);
        int low0 = (int)floorf(c);
        int lim  = (int)limit;
        bool cap = (low0 >= lim - 1);
        int low  = cap ? lim - 1 : low0;
        int high = cap ? lim - 1 : low0 + 1;
        if (cap) c = (float)low;
        float l = c - (float)low;
        float h = 1.0f - l;
        if (axis) { s_xl[n] = low;     s_xh[n] = high;     s_wx0[n] = h*valid; s_wx1[n] = l*valid; }
        else      { s_yl[n] = low * W; s_yh[n] = high * W; s_wy0[n] = h*valid; s_wy1[n] = l*valid; }
    }
    __syncthreads();

    // Lane-resident x tap: lane l<28 -> sample l>>1, corner l&1.
    const int ll   = (lane < 28) ? lane : 27;
    const int nx   = ll >> 1;
    const int xoff = (ll & 1) ? s_xh[nx] : s_xl[nx];
    const float wx = (lane < 28)
                   ? (((lane & 1) ? s_wx1[nx] : s_wx0[nx]) * 0.25f)
                   : 0.0f;

    // After the 4-lane bin reduction, lanes 0,4,..,24 hold pw=0..6; their
    // output addresses are contiguous floats -> single-wavefront STG.
    const bool wlane = (lane < 28) && ((lane & 3) == 0);
    const int  pw    = lane >> 2;

    const long long plane = (long long)H * W;
    const float* __restrict__ xb = x + (long long)s_bidx * C * plane + xoff;
    const int cend = cbase + C / CSPLIT;

    for (int c0 = cbase + warp * CPW; c0 < cend; c0 += NWARP * CPW) {
        const float* __restrict__ base0 = xb + (long long)(c0 + 0) * plane;
        const float* __restrict__ base1 = xb + (long long)(c0 + 1) * plane;
        const float* __restrict__ base2 = xb + (long long)(c0 + 2) * plane;
        const float* __restrict__ base3 = xb + (long long)(c0 + 3) * plane;
        float* o = out + ((long long)k * C + c0) * 49 + pw;
        #pragma unroll
        for (int ph = 0; ph < PHN; ph++) {
            float a0 = 0.0f, a1 = 0.0f, a2 = 0.0f, a3 = 0.0f;
            #pragma unroll
            for (int j = 0; j < 4; j++) {
                int ny     = 2*ph + (j >> 1);
                int   yoff = (j & 1) ? s_yh[ny]  : s_yl[ny];
                float wy   = (j & 1) ? s_wy1[ny] : s_wy0[ny];
                float v0 = __ldg(base0 + yoff);
                float v1 = __ldg(base1 + yoff);
                float v2 = __ldg(base2 + yoff);
                float v3 = __ldg(base3 + yoff);
                a0 = fmaf(wy, v0, a0);
                a1 = fmaf(wy, v1, a1);
                a2 = fmaf(wy, v2, a2);
                a3 = fmaf(wy, v3, a3);
            }
            a0 *= wx;  a1 *= wx;  a2 *= wx;  a3 *= wx;
            a0 += __shfl_xor_sync(0xffffffffu, a0, 1);
            a1 += __shfl_xor_sync(0xffffffffu, a1, 1);
            a2 += __shfl_xor_sync(0xffffffffu, a2, 1);
            a3 += __shfl_xor_sync(0xffffffffu, a3, 1);
            a0 += __shfl_xor_sync(0xffffffffu, a0, 2);
            a1 += __shfl_xor_sync(0xffffffffu, a1, 2);
            a2 += __shfl_xor_sync(0xffffffffu, a2, 2);
            a3 += __shfl_xor_sync(0xffffffffu, a3, 2);
            if (wlane) {
                o[ph * 7]          = a0;
                o[49 + ph * 7]     = a1;
                o[2 * 49 + ph * 7] = a2;
                o[3 * 49 + ph * 7] = a3;
            }
        }
    }
}

extern "C" void kernel_launch(void* const* d_in, const int* in_sizes, int n_in,
                              void* d_out, int out_size)
{
    const float* x    = (const float*)d_in[0];
    const float* rois = (const float*)d_in[1];
    float* out        = (float*)d_out;
    const int K = in_sizes[1] / 5;
    roialign_kernel<<<K * CSPLIT, TPB>>>(x, rois, out, 256, 200, 200);
}

// round 7
// speedup vs baseline: 1.3969x; 1.0121x over previous
#include <cuda_runtime.h>

#define PHN 7
#define NSAMP 14          // PH * sampling_ratio
#define TPB 256
#define NWARP (TPB/32)
#define CPW 4             // channels per warp iteration
#define CSPLIT 2          // blocks per roi (channel split)

__global__ __launch_bounds__(TPB, 3) void roialign_kernel(
    const float* __restrict__ x, const float* __restrict__ rois,
    float* __restrict__ out, int C, int H, int W)
{
    __shared__ int   s_yl[NSAMP], s_yh[NSAMP];     // pre-multiplied by W
    __shared__ float s_wy0[NSAMP], s_wy1[NSAMP];
    __shared__ int   s_xl[NSAMP], s_xh[NSAMP];
    __shared__ float s_wx0[NSAMP], s_wx1[NSAMP];
    __shared__ int   s_bidx;

    const int k     = blockIdx.x / CSPLIT;
    const int cbase = (blockIdx.x % CSPLIT) * (C / CSPLIT);
    const int tid  = threadIdx.x;
    const int lane = tid & 31;
    const int warp = tid >> 5;

    if (tid == 0) s_bidx = (int)rois[k*5];
    // Per-axis sample tables, matching reference _axis() exactly.
    if (tid < 2*NSAMP) {
        int axis = tid / NSAMP;            // 0 = y, 1 = x
        int n    = tid % NSAMP;
        float limit = axis ? (float)W : (float)H;
        float start = rois[k*5 + (axis ? 1 : 2)] * 0.25f - 0.5f;
        float end   = rois[k*5 + (axis ? 3 : 4)] * 0.25f - 0.5f;
        float bin   = (end - start) * (1.0f/7.0f);
        int p = n >> 1, s = n & 1;
        float coord = start + ((float)p + ((float)s + 0.5f) * 0.5f) * bin;
        float valid = (coord >= -1.0f && coord <= limit) ? 1.0f : 0.0f;
        float c = fmaxf(coord, 0.0f);
        int low0 = (int)floorf(c);
        int lim  = (int)limit;
        bool cap = (low0 >= lim - 1);
        int low  = cap ? lim - 1 : low0;
        int high = cap ? lim - 1 : low0 + 1;
        if (cap) c = (float)low;
        float l = c - (float)low;
        float h = 1.0f - l;
        if (axis) { s_xl[n] = low;     s_xh[n] = high;     s_wx0[n] = h*valid; s_wx1[n] = l*valid; }
        else      { s_yl[n] = low * W; s_yh[n] = high * W; s_wy0[n] = h*valid; s_wy1[n] = l*valid; }
    }
    __syncthreads();

    // Lane-resident x tap: lane l<28 -> sample l>>1, corner l&1.
    const int ll   = (lane < 28) ? lane : 27;
    const int nx   = ll >> 1;
    const int xoff = (ll & 1) ? s_xh[nx] : s_xl[nx];
    const float wx = (lane < 28)
                   ? (((lane & 1) ? s_wx1[nx] : s_wx0[nx]) * 0.25f)
                   : 0.0f;

    // After the 4-lane bin reduction, lanes 0,4,..,24 hold pw=0..6; their
    // output addresses are contiguous floats -> single-wavefront STG.
    const bool wlane = (lane < 28) && ((lane & 3) == 0);
    const int  pw    = lane >> 2;

    const long long plane = (long long)H * W;
    const float* __restrict__ xb = x + (long long)s_bidx * C * plane + xoff;
    const int cend = cbase + C / CSPLIT;

    for (int c0 = cbase + warp * CPW; c0 < cend; c0 += NWARP * CPW) {
        const float* __restrict__ base0 = xb + (long long)(c0 + 0) * plane;
        const float* __restrict__ base1 = xb + (long long)(c0 + 1) * plane;
        const float* __restrict__ base2 = xb + (long long)(c0 + 2) * plane;
        const float* __restrict__ base3 = xb + (long long)(c0 + 3) * plane;
        float* o = out + ((long long)k * C + c0) * 49 + pw;
        #pragma unroll
        for (int ph = 0; ph < PHN; ph++) {
            float a0 = 0.0f, a1 = 0.0f, a2 = 0.0f, a3 = 0.0f;
            #pragma unroll
            for (int j = 0; j < 4; j++) {
                int ny     = 2*ph + (j >> 1);
                int   yoff = (j & 1) ? s_yh[ny]  : s_yl[ny];
                float wy   = (j & 1) ? s_wy1[ny] : s_wy0[ny];
                float v0 = __ldg(base0 + yoff);
                float v1 = __ldg(base1 + yoff);
                float v2 = __ldg(base2 + yoff);
                float v3 = __ldg(base3 + yoff);
                a0 = fmaf(wy, v0, a0);
                a1 = fmaf(wy, v1, a1);
                a2 = fmaf(wy, v2, a2);
                a3 = fmaf(wy, v3, a3);
            }
            a0 *= wx;  a1 *= wx;  a2 *= wx;  a3 *= wx;
            a0 += __shfl_xor_sync(0xffffffffu, a0, 1);
            a1 += __shfl_xor_sync(0xffffffffu, a1, 1);
            a2 += __shfl_xor_sync(0xffffffffu, a2, 1);
            a3 += __shfl_xor_sync(0xffffffffu, a3, 1);
            a0 += __shfl_xor_sync(0xffffffffu, a0, 2);
            a1 += __shfl_xor_sync(0xffffffffu, a1, 2);
            a2 += __shfl_xor_sync(0xffffffffu, a2, 2);
            a3 += __shfl_xor_sync(0xffffffffu, a3, 2);
            if (wlane) {
                o[ph * 7]          = a0;
                o[49 + ph * 7]     = a1;
                o[2 * 49 + ph * 7] = a2;
                o[3 * 49 + ph * 7] = a3;
            }
        }
    }
}

extern "C" void kernel_launch(void* const* d_in, const int* in_sizes, int n_in,
                              void* d_out, int out_size)
{
    const float* x    = (const float*)d_in[0];
    const float* rois = (const float*)d_in[1];
    float* out        = (float*)d_out;
    const int K = in_sizes[1] / 5;
    roialign_kernel<<<K * CSPLIT, TPB>>>(x, rois, out, 256, 200, 200);
}